// round 13
// baseline (speedup 1.0000x reference)
#include <cuda_runtime.h>

#define Bv 2
#define Cv 64
#define Nv 1024
#define Ev 32
#define TI 16                // i-rows per edge block (best measured)
#define NCHUNK 8             // n-chunks of 128 per be
#define NPROD (Bv * Ev * NCHUNK)             // 512 producer blocks
#define NEDGE (Bv * Ev * (Nv / TI))          // 4096 edge blocks

// Scratch: PRE-DOUBLED projected node features 2*t1, 2*t2: (B*E, N) each.
__device__ float g_t1[Bv * Ev * Nv];
__device__ float g_t2[Bv * Ev * Nv];
// Per-(be,chunk) ready flags. Idempotent (=1): stale-set on graph replays is a
// benign identical-value race (proj rewrites bit-identical data).
__device__ int g_flag[NPROD];

__device__ __forceinline__ float tanh_approx(float x) {
    float y;
    asm("tanh.approx.f32 %0, %1;" : "=f"(y) : "f"(x));
    return y;
}

__device__ __forceinline__ int ld_acquire_gpu(const int* p) {
    int v;
    asm volatile("ld.acquire.gpu.global.b32 %0, [%1];" : "=r"(v) : "l"(p) : "memory");
    return v;
}

__device__ __forceinline__ void st_release_gpu(int* p, int v) {
    asm volatile("st.release.gpu.global.b32 [%0], %1;" :: "l"(p), "r"(v) : "memory");
}

// out = relu(m1) * sigmoid(relu(m2))
__device__ __forceinline__ float edge_elem(float m1, float m2) {
    float a  = fmaxf(m1, 0.0f);
    float xr = fmaxf(m2, 0.0f);
    float h  = tanh_approx(0.5f * xr);
    float t  = 0.5f * a;
    return fmaf(t, h, t);               // 0.5*a*(h+1) == a * sigmoid(xr)
}

// ---------------------------------------------------------------------------
// Fused kernel, 1-D grid of NPROD + NEDGE blocks.  (R12 configuration —
// measured-best kernel 40.35us; R9/R11 perturbations of the consumer loop
// both regressed, so that loop is untouched.)
//   bid <  NPROD : producer, c-split critical path: 128 n-values per block,
//                  threads 0-127 accumulate c in [0,32), threads 128-255
//                  c in [32,64); one smem reduction combines. 32 serial
//                  loads/thread. Release protocol: t stores -> bar.sync
//                  (block-level happens-before) -> st.release.gpu flag;
//                  consumers pair with ld.acquire.gpu. (Replaces the
//                  __threadfence: one fewer MEMBAR.GPU on the lead-in path.)
//   bid >= NPROD : consumer — acquire be's 8 chunk-flags, write TI=16 rows
//                  (scalar ti broadcasts, per-row diagonal fix, streaming
//                  stores). This loop shape is the one ptxas paces best.
// All producers land in wave 1; later waves stream with flags pre-set.
// ---------------------------------------------------------------------------
__global__ void __launch_bounds__(256, 8) fused_kernel(
    const float* __restrict__ emb,
    const float* __restrict__ th12_1,
    const float* __restrict__ th12_2,
    const float* __restrict__ th5_1,
    const float* __restrict__ th5_2,
    float* __restrict__ out) {

    const int bid = blockIdx.x;

    if (bid < NPROD) {
        // ---- producer ----
        const int be = bid >> 3;            // 0..63
        const int nc = bid & 7;             // n-chunk 0..7
        const int b  = be / Ev;
        const int e  = be % Ev;

        __shared__ float w1[Cv];
        __shared__ float w2[Cv];
        __shared__ float p1[128];
        __shared__ float p2[128];
        if (threadIdx.x < Cv) {
            // fold the reference's "m + m" doubling into the weights
            w1[threadIdx.x] = 2.0f * th12_1[e * Cv + threadIdx.x];
            w2[threadIdx.x] = 2.0f * th12_2[e * Cv + threadIdx.x];
        }
        __syncthreads();

        const int nl = threadIdx.x & 127;   // local n 0..127
        const int ch = threadIdx.x >> 7;    // c-half 0..1
        const int n  = nc * 128 + nl;
        const int c0 = ch * (Cv / 2);

        const float* ebase = emb + (size_t)b * Cv * Nv + (size_t)c0 * Nv + n;
        float s1 = 0.0f, s2 = 0.0f;
#pragma unroll
        for (int c = 0; c < Cv / 2; ++c) {  // 32 fully-unrolled loads
            float x = ebase[(size_t)c * Nv];
            s1 = fmaf(w1[c0 + c], x, s1);
            s2 = fmaf(w2[c0 + c], x, s2);
        }

        if (ch == 1) { p1[nl] = s1; p2[nl] = s2; }
        __syncthreads();
        if (ch == 0) {
            g_t1[be * Nv + n] = s1 + p1[nl];
            g_t2[be * Nv + n] = s2 + p2[nl];
        }

        __syncthreads();                    // t stores happen-before below
        if (threadIdx.x == 0) {
            st_release_gpu(&g_flag[bid], 1);  // release: pairs w/ ld.acquire
        }
        return;
    }

    // ---- consumer (edge) ----
    const int eid = bid - NPROD;
    const int be  = eid / (Nv / TI);         // 0..63 (be-major sweep)
    const int xc  = eid % (Nv / TI);         // 0..63
    const int e   = be % Ev;

    if (threadIdx.x < NCHUNK) {
        const int* f = &g_flag[be * NCHUNK + threadIdx.x];
        while (ld_acquire_gpu(f) == 0) { __nanosleep(64); }
    }
    __syncthreads();

    const float* __restrict__ r1 = g_t1 + be * Nv;
    const float* __restrict__ r2 = g_t2 + be * Nv;

    const int i0 = xc * TI;
    const int j0 = threadIdx.x * 4;
    const float4 tj1 = *reinterpret_cast<const float4*>(r1 + j0);
    const float4 tj2 = *reinterpret_cast<const float4*>(r2 + j0);

    float* dst = out + (((size_t)be * Nv) + i0) * Nv + j0;

#pragma unroll
    for (int r = 0; r < TI; ++r) {
        const int i = i0 + r;
        const float ti1 = r1[i];            // uniform broadcast (L1-hot)
        const float ti2 = r2[i];

        float4 o;
        o.x = edge_elem(fmaxf(ti1, tj1.x), fmaxf(ti2, tj2.x));
        o.y = edge_elem(fmaxf(ti1, tj1.y), fmaxf(ti2, tj2.y));
        o.z = edge_elem(fmaxf(ti1, tj1.z), fmaxf(ti2, tj2.z));
        o.w = edge_elem(fmaxf(ti1, tj1.w), fmaxf(ti2, tj2.w));

        // Diagonal fix: only the thread whose 4-wide slice contains column i.
        const unsigned k = (unsigned)(i - j0);
        if (k < 4u) {
            const float a5 = th5_1[e];
            const float g5 = th5_2[e];
            float v = edge_elem(ti1 + a5, ti2 + g5);  // max(Ti,Tj)==Ti on diag
            if      (k == 0u) o.x = v;
            else if (k == 1u) o.y = v;
            else if (k == 2u) o.z = v;
            else              o.w = v;
        }

        __stcs(reinterpret_cast<float4*>(dst), o);   // streaming store
        dst += Nv;
    }
}

// ---------------------------------------------------------------------------
// Launch. Resolve input indices defensively from in_sizes:
//   dict order:   sizes [BCN, EC, EC, E, EC, EC, E] -> th5 at 3 and 6
//   sorted order: sizes [BCN, EC, EC, EC, EC, E, E] -> th5 at 5 and 6
// ---------------------------------------------------------------------------
extern "C" void kernel_launch(void* const* d_in, const int* in_sizes, int n_in,
                              void* d_out, int out_size) {
    const float* emb = (const float*)d_in[0];
    const float *th12_1, *th5_1, *th12_2, *th5_2;

    if (n_in >= 7 && in_sizes[3] == Ev) {
        th12_1 = (const float*)d_in[1];
        th5_1  = (const float*)d_in[3];
        th12_2 = (const float*)d_in[4];
        th5_2  = (const float*)d_in[6];
    } else {
        th12_1 = (const float*)d_in[1];
        th12_2 = (const float*)d_in[2];
        th5_1  = (const float*)d_in[5];
        th5_2  = (const float*)d_in[6];
    }

    float* out = (float*)d_out;

    fused_kernel<<<NPROD + NEDGE, 256>>>(emb, th12_1, th12_2, th5_1, th5_2, out);
}

// round 14
// speedup vs baseline: 1.0015x; 1.0015x over previous
#include <cuda_runtime.h>

#define Bv 2
#define Cv 64
#define Nv 1024
#define Ev 32
#define TI 16                // i-rows per edge block (best measured)
#define NCHUNK 8             // n-chunks of 128 per be
#define NPROD (Bv * Ev * NCHUNK)             // 512 producer blocks
#define NEDGE (Bv * Ev * (Nv / TI))          // 4096 edge blocks

// Scratch: PRE-DOUBLED projected node features 2*t1, 2*t2: (B*E, N) each.
__device__ float g_t1[Bv * Ev * Nv];
__device__ float g_t2[Bv * Ev * Nv];
// Per-(be,chunk) ready flags. Idempotent (=1): stale-set on graph replays is a
// benign identical-value race (proj rewrites bit-identical data).
__device__ int g_flag[NPROD];

__device__ __forceinline__ float tanh_approx(float x) {
    float y;
    asm("tanh.approx.f32 %0, %1;" : "=f"(y) : "f"(x));
    return y;
}

__device__ __forceinline__ int ld_acquire_gpu(const int* p) {
    int v;
    asm volatile("ld.acquire.gpu.global.b32 %0, [%1];" : "=r"(v) : "l"(p) : "memory");
    return v;
}

__device__ __forceinline__ void st_release_gpu(int* p, int v) {
    asm volatile("st.release.gpu.global.b32 [%0], %1;" :: "l"(p), "r"(v) : "memory");
}

// out = relu(m1) * sigmoid(relu(m2))
__device__ __forceinline__ float edge_elem(float m1, float m2) {
    float a  = fmaxf(m1, 0.0f);
    float xr = fmaxf(m2, 0.0f);
    float h  = tanh_approx(0.5f * xr);
    float t  = 0.5f * a;
    return fmaf(t, h, t);               // 0.5*a*(h+1) == a * sigmoid(xr)
}

// ---------------------------------------------------------------------------
// Fused kernel, 1-D grid of NPROD + NEDGE blocks.  FINAL configuration:
// measured-best kernel band 40.35-41.1us (R10/R12/R13); all consumer-loop
// perturbations (TI=32, vectorized ti) regressed — loop shape is optimal.
// Steady state runs at the measured pure-write ceiling (~6.8 TB/s); lead-in
// (~0.8us) is DRAM-latency-bound via the c-split producer.
//   bid <  NPROD : producer, c-split critical path: 128 n-values per block,
//                  threads 0-127 accumulate c in [0,32), threads 128-255
//                  c in [32,64); one smem reduction combines. 32 serial
//                  loads/thread. Release: t stores -> bar.sync ->
//                  st.release.gpu flag (pairs with consumer ld.acquire.gpu).
//   bid >= NPROD : consumer — acquire be's 8 chunk-flags, write TI=16 rows
//                  (scalar ti broadcasts, per-row diagonal fix, streaming
//                  stores).
// All producers land in wave 1; later waves stream with flags pre-set.
// ---------------------------------------------------------------------------
__global__ void __launch_bounds__(256, 8) fused_kernel(
    const float* __restrict__ emb,
    const float* __restrict__ th12_1,
    const float* __restrict__ th12_2,
    const float* __restrict__ th5_1,
    const float* __restrict__ th5_2,
    float* __restrict__ out) {

    const int bid = blockIdx.x;

    if (bid < NPROD) {
        // ---- producer ----
        const int be = bid >> 3;            // 0..63
        const int nc = bid & 7;             // n-chunk 0..7
        const int b  = be / Ev;
        const int e  = be % Ev;

        __shared__ float w1[Cv];
        __shared__ float w2[Cv];
        __shared__ float p1[128];
        __shared__ float p2[128];
        if (threadIdx.x < Cv) {
            // fold the reference's "m + m" doubling into the weights
            w1[threadIdx.x] = 2.0f * th12_1[e * Cv + threadIdx.x];
            w2[threadIdx.x] = 2.0f * th12_2[e * Cv + threadIdx.x];
        }
        __syncthreads();

        const int nl = threadIdx.x & 127;   // local n 0..127
        const int ch = threadIdx.x >> 7;    // c-half 0..1
        const int n  = nc * 128 + nl;
        const int c0 = ch * (Cv / 2);

        const float* ebase = emb + (size_t)b * Cv * Nv + (size_t)c0 * Nv + n;
        float s1 = 0.0f, s2 = 0.0f;
#pragma unroll
        for (int c = 0; c < Cv / 2; ++c) {  // 32 fully-unrolled loads
            float x = ebase[(size_t)c * Nv];
            s1 = fmaf(w1[c0 + c], x, s1);
            s2 = fmaf(w2[c0 + c], x, s2);
        }

        if (ch == 1) { p1[nl] = s1; p2[nl] = s2; }
        __syncthreads();
        if (ch == 0) {
            g_t1[be * Nv + n] = s1 + p1[nl];
            g_t2[be * Nv + n] = s2 + p2[nl];
        }

        __syncthreads();                    // t stores happen-before below
        if (threadIdx.x == 0) {
            st_release_gpu(&g_flag[bid], 1);  // release: pairs w/ ld.acquire
        }
        return;
    }

    // ---- consumer (edge) ----
    const int eid = bid - NPROD;
    const int be  = eid / (Nv / TI);         // 0..63 (be-major sweep)
    const int xc  = eid % (Nv / TI);         // 0..63
    const int e   = be % Ev;

    if (threadIdx.x < NCHUNK) {
        const int* f = &g_flag[be * NCHUNK + threadIdx.x];
        while (ld_acquire_gpu(f) == 0) { __nanosleep(64); }
    }
    __syncthreads();

    const float* __restrict__ r1 = g_t1 + be * Nv;
    const float* __restrict__ r2 = g_t2 + be * Nv;

    const int i0 = xc * TI;
    const int j0 = threadIdx.x * 4;
    const float4 tj1 = *reinterpret_cast<const float4*>(r1 + j0);
    const float4 tj2 = *reinterpret_cast<const float4*>(r2 + j0);

    float* dst = out + (((size_t)be * Nv) + i0) * Nv + j0;

#pragma unroll
    for (int r = 0; r < TI; ++r) {
        const int i = i0 + r;
        const float ti1 = r1[i];            // uniform broadcast (L1-hot)
        const float ti2 = r2[i];

        float4 o;
        o.x = edge_elem(fmaxf(ti1, tj1.x), fmaxf(ti2, tj2.x));
        o.y = edge_elem(fmaxf(ti1, tj1.y), fmaxf(ti2, tj2.y));
        o.z = edge_elem(fmaxf(ti1, tj1.z), fmaxf(ti2, tj2.z));
        o.w = edge_elem(fmaxf(ti1, tj1.w), fmaxf(ti2, tj2.w));

        // Diagonal fix: only the thread whose 4-wide slice contains column i.
        const unsigned k = (unsigned)(i - j0);
        if (k < 4u) {
            const float a5 = th5_1[e];
            const float g5 = th5_2[e];
            float v = edge_elem(ti1 + a5, ti2 + g5);  // max(Ti,Tj)==Ti on diag
            if      (k == 0u) o.x = v;
            else if (k == 1u) o.y = v;
            else if (k == 2u) o.z = v;
            else              o.w = v;
        }

        __stcs(reinterpret_cast<float4*>(dst), o);   // streaming store
        dst += Nv;
    }
}

// ---------------------------------------------------------------------------
// Launch. Resolve input indices defensively from in_sizes:
//   dict order:   sizes [BCN, EC, EC, E, EC, EC, E] -> th5 at 3 and 6
//   sorted order: sizes [BCN, EC, EC, EC, EC, E, E] -> th5 at 5 and 6
// ---------------------------------------------------------------------------
extern "C" void kernel_launch(void* const* d_in, const int* in_sizes, int n_in,
                              void* d_out, int out_size) {
    const float* emb = (const float*)d_in[0];
    const float *th12_1, *th5_1, *th12_2, *th5_2;

    if (n_in >= 7 && in_sizes[3] == Ev) {
        th12_1 = (const float*)d_in[1];
        th5_1  = (const float*)d_in[3];
        th12_2 = (const float*)d_in[4];
        th5_2  = (const float*)d_in[6];
    } else {
        th12_1 = (const float*)d_in[1];
        th12_2 = (const float*)d_in[2];
        th5_1  = (const float*)d_in[5];
        th5_2  = (const float*)d_in[6];
    }

    float* out = (float*)d_out;

    fused_kernel<<<NPROD + NEDGE, 256>>>(emb, th12_1, th12_2, th5_1, th5_2, out);
}